// round 3
// baseline (speedup 1.0000x reference)
#include <cuda_runtime.h>
#include <math.h>

#define T_LEN   16
#define C_DIM   192
#define DIN     384
#define DSTATE  16
#define DTRANK  12
#define XP_OUT  44
#define HW      784
#define NTHR    384
#define TSTR    20      // [c][t] stride: 16 t + pad, multiple of 4 for LDS.128

__device__ __forceinline__ float siluf(float v) {
    return __fdividef(v, 1.0f + __expf(-v));
}

__global__ __launch_bounds__(NTHR, 1)
void mamba_fused_kernel(const float* __restrict__ x,
                        const float* __restrict__ norm_w,
                        const float* __restrict__ in_proj_w,   // (192, 768)
                        const float* __restrict__ conv_w,      // (384, 4)
                        const float* __restrict__ conv_b,      // (384,)
                        const float* __restrict__ x_proj_w,    // (384, 44)
                        const float* __restrict__ dt_proj_w,   // (12, 384)
                        const float* __restrict__ dt_proj_b,   // (384,)
                        const float* __restrict__ A_log,       // (384, 16)
                        const float* __restrict__ Dp,          // (384,)
                        const float* __restrict__ out_proj_w,  // (384, 192)
                        float* __restrict__ out)
{
    extern __shared__ float sm[];
    float* s_xn = sm;                      // [c][t] 192*20 = 3840
    float* s_u  = s_xn + C_DIM * TSTR;     // [t][c] 16*384 = 6144
    float* s_z  = s_u  + T_LEN * DIN;      // 6144
    float* s_uc = s_z  + T_LEN * DIN;      // 6144
    float* s_dt = s_uc + T_LEN * DIN;      // 6144
    float* s_db = s_dt + T_LEN * DIN;      // 16*44 = 704
    float* s_yT = sm;                      // [c][t] 384*20 = 7680, aliases xn+u (dead)
    // total 29120 floats = 116480 B

    const int tid  = threadIdx.x;
    const int lane = tid & 31;
    const int wid  = tid >> 5;

    const int n  = blockIdx.x;
    const int b  = n / HW;
    const int hw = n - b * HW;
    const size_t tstride = (size_t)HW * C_DIM;
    const size_t base0   = ((size_t)b * T_LEN * HW + hw) * C_DIM;

    // ---------------- Phase A: load + RMSNorm -> s_xn[c][t] ----------------
    for (int t = wid; t < T_LEN; t += 12) {
        const float* row = x + base0 + (size_t)t * tstride;
        float v[6];
        float ss = 0.f;
        #pragma unroll
        for (int i = 0; i < 6; i++) { v[i] = row[lane + 32 * i]; ss = fmaf(v[i], v[i], ss); }
        #pragma unroll
        for (int o = 16; o; o >>= 1) ss += __shfl_xor_sync(0xffffffffu, ss, o);
        float nrm = rsqrtf(ss * (1.0f / 192.0f) + 1e-6f);
        #pragma unroll
        for (int i = 0; i < 6; i++) {
            int c = lane + 32 * i;
            s_xn[c * TSTR + t] = v[i] * nrm * norm_w[c];
        }
    }
    __syncthreads();

    // ---------------- Phase B: in_proj (16x192 @ 192x768) -> u, silu(z) ----
    // thread col = tid handles output columns {tid, tid+384}; all 16 t.
    {
        float acc0[16], acc1[16];
        #pragma unroll
        for (int t = 0; t < 16; t++) { acc0[t] = 0.f; acc1[t] = 0.f; }
        #pragma unroll 2
        for (int k = 0; k < C_DIM; k++) {
            const float w0 = in_proj_w[k * 768 + tid];
            const float w1 = in_proj_w[k * 768 + tid + 384];
            const float4* xp = (const float4*)(s_xn + k * TSTR);
            #pragma unroll
            for (int q = 0; q < 4; q++) {
                float4 xv = xp[q];
                acc0[4*q+0] = fmaf(xv.x, w0, acc0[4*q+0]);
                acc0[4*q+1] = fmaf(xv.y, w0, acc0[4*q+1]);
                acc0[4*q+2] = fmaf(xv.z, w0, acc0[4*q+2]);
                acc0[4*q+3] = fmaf(xv.w, w0, acc0[4*q+3]);
                acc1[4*q+0] = fmaf(xv.x, w1, acc1[4*q+0]);
                acc1[4*q+1] = fmaf(xv.y, w1, acc1[4*q+1]);
                acc1[4*q+2] = fmaf(xv.z, w1, acc1[4*q+2]);
                acc1[4*q+3] = fmaf(xv.w, w1, acc1[4*q+3]);
            }
        }
        #pragma unroll
        for (int t = 0; t < 16; t++) {
            s_u[t * DIN + tid] = acc0[t];
            s_z[t * DIN + tid] = siluf(acc1[t]);
        }
    }
    __syncthreads();

    // ---------------- Phase C: causal depthwise conv + silu -> s_uc --------
    {
        const int c = tid;
        const float4 cw = *(const float4*)(conv_w + c * 4);
        const float cb = conv_b[c];
        float um3 = 0.f, um2 = 0.f, um1 = 0.f;
        #pragma unroll
        for (int t = 0; t < T_LEN; t++) {
            float u0 = s_u[t * DIN + c];
            float acc = cb;
            acc = fmaf(um3, cw.x, acc);
            acc = fmaf(um2, cw.y, acc);
            acc = fmaf(um1, cw.z, acc);
            acc = fmaf(u0,  cw.w, acc);
            s_uc[t * DIN + c] = siluf(acc);
            um3 = um2; um2 = um1; um1 = u0;
        }
    }
    __syncthreads();

    // ---------------- Phase D: x_proj (16x384 @ 384x44) -> s_db ------------
    // warp handles timestep t (warps 0..3 also t+12). lanes: j=lane, j2=lane+32.
    for (int t = wid; t < T_LEN; t += 12) {
        const float* ucr = s_uc + t * DIN;
        const int j  = lane;          // 0..31  (<44)
        const int j2 = lane + 32;     // 32..63 (valid if <44)
        const bool has2 = (j2 < XP_OUT);
        float a1 = 0.f, a2 = 0.f;
        #pragma unroll 4
        for (int k = 0; k < DIN; k += 4) {
            float4 uv = *(const float4*)(ucr + k);
            a1 = fmaf(uv.x, x_proj_w[(k + 0) * XP_OUT + j], a1);
            a1 = fmaf(uv.y, x_proj_w[(k + 1) * XP_OUT + j], a1);
            a1 = fmaf(uv.z, x_proj_w[(k + 2) * XP_OUT + j], a1);
            a1 = fmaf(uv.w, x_proj_w[(k + 3) * XP_OUT + j], a1);
            if (has2) {
                a2 = fmaf(uv.x, x_proj_w[(k + 0) * XP_OUT + j2], a2);
                a2 = fmaf(uv.y, x_proj_w[(k + 1) * XP_OUT + j2], a2);
                a2 = fmaf(uv.z, x_proj_w[(k + 2) * XP_OUT + j2], a2);
                a2 = fmaf(uv.w, x_proj_w[(k + 3) * XP_OUT + j2], a2);
            }
        }
        s_db[t * XP_OUT + j] = a1;
        if (has2) s_db[t * XP_OUT + j2] = a2;
    }
    __syncthreads();

    // ---------------- Phase E: dt_proj + softplus -> s_dt ------------------
    {
        const int c = tid;
        float wreg[DTRANK];
        #pragma unroll
        for (int r = 0; r < DTRANK; r++) wreg[r] = dt_proj_w[r * DIN + c];
        const float bias = dt_proj_b[c];
        #pragma unroll
        for (int t = 0; t < T_LEN; t++) {
            const float* dr = s_db + t * XP_OUT;
            float acc = bias;
            #pragma unroll
            for (int r = 0; r < DTRANK; r++)
                acc = fmaf(dr[r], wreg[r], acc);
            float sp = (acc > 20.f) ? acc : log1pf(__expf(acc));
            s_dt[t * DIN + c] = sp;
        }
    }
    __syncthreads();

    // ---------------- Phase F: selective scan -> s_yT[c][t] ----------------
    {
        const int c = tid;
        float A[DSTATE];
        {
            const float4* Ap = (const float4*)(A_log + c * DSTATE);
            #pragma unroll
            for (int q = 0; q < 4; q++) {
                float4 av = Ap[q];
                A[4*q+0] = -__expf(av.x); A[4*q+1] = -__expf(av.y);
                A[4*q+2] = -__expf(av.z); A[4*q+3] = -__expf(av.w);
            }
        }
        float h[DSTATE];
        #pragma unroll
        for (int s = 0; s < DSTATE; s++) h[s] = 0.f;
        const float Dc = Dp[c];

        #pragma unroll 1
        for (int t = 0; t < T_LEN; t++) {
            float dtv = s_dt[t * DIN + c];
            float ucv = s_uc[t * DIN + c];
            float du  = dtv * ucv;
            const float4* B4 = (const float4*)(s_db + t * XP_OUT + DTRANK);
            const float4* C4 = (const float4*)(s_db + t * XP_OUT + DTRANK + DSTATE);
            float y = 0.f;
            #pragma unroll
            for (int q = 0; q < 4; q++) {
                float4 Bv = B4[q];
                float4 Cv = C4[q];
                float dA, hb;
                dA = __expf(dtv * A[4*q+0]); hb = fmaf(h[4*q+0], dA, du * Bv.x); h[4*q+0] = hb; y = fmaf(hb, Cv.x, y);
                dA = __expf(dtv * A[4*q+1]); hb = fmaf(h[4*q+1], dA, du * Bv.y); h[4*q+1] = hb; y = fmaf(hb, Cv.y, y);
                dA = __expf(dtv * A[4*q+2]); hb = fmaf(h[4*q+2], dA, du * Bv.z); h[4*q+2] = hb; y = fmaf(hb, Cv.z, y);
                dA = __expf(dtv * A[4*q+3]); hb = fmaf(h[4*q+3], dA, du * Bv.w); h[4*q+3] = hb; y = fmaf(hb, Cv.w, y);
            }
            y = fmaf(ucv, Dc, y);
            // stage y*silu(z) to registers then write after sync barrier below
            s_dt[t * DIN + c] = y * s_z[t * DIN + c];   // reuse s_dt as y[t][c] temp
        }
    }
    __syncthreads();
    // transpose y[t][c] -> s_yT[c][t] (s_yT aliases dead xn/u region)
    {
        const int c = tid;
        #pragma unroll
        for (int t = 0; t < T_LEN; t++)
            s_yT[c * TSTR + t] = s_dt[t * DIN + c];
    }
    __syncthreads();

    // ---------------- Phase G: out_proj (16x384 @ 384x192) + residual ------
    {
        const int c    = (tid < C_DIM) ? tid : (tid - C_DIM);
        const int t0   = (tid < C_DIM) ? 0 : 8;
        float acc[8];
        #pragma unroll
        for (int i = 0; i < 8; i++) acc[i] = 0.f;
        #pragma unroll 2
        for (int k = 0; k < DIN; k++) {
            const float w = out_proj_w[k * C_DIM + c];
            const float4* yp = (const float4*)(s_yT + k * TSTR + t0);
            float4 y0 = yp[0];
            float4 y1 = yp[1];
            acc[0] = fmaf(y0.x, w, acc[0]);
            acc[1] = fmaf(y0.y, w, acc[1]);
            acc[2] = fmaf(y0.z, w, acc[2]);
            acc[3] = fmaf(y0.w, w, acc[3]);
            acc[4] = fmaf(y1.x, w, acc[4]);
            acc[5] = fmaf(y1.y, w, acc[5]);
            acc[6] = fmaf(y1.z, w, acc[6]);
            acc[7] = fmaf(y1.w, w, acc[7]);
        }
        #pragma unroll
        for (int i = 0; i < 8; i++) {
            size_t g = base0 + (size_t)(t0 + i) * tstride + c;
            out[g] = x[g] + acc[i];
        }
    }
}

extern "C" void kernel_launch(void* const* d_in, const int* in_sizes, int n_in,
                              void* d_out, int out_size)
{
    (void)in_sizes; (void)n_in; (void)out_size;
    const float* x         = (const float*)d_in[0];
    const float* norm_w    = (const float*)d_in[1];
    const float* in_proj_w = (const float*)d_in[2];
    const float* conv_w    = (const float*)d_in[3];
    const float* conv_b    = (const float*)d_in[4];
    const float* x_proj_w  = (const float*)d_in[5];
    const float* dt_proj_w = (const float*)d_in[6];
    const float* dt_proj_b = (const float*)d_in[7];
    const float* A_log     = (const float*)d_in[8];
    const float* Dp        = (const float*)d_in[9];
    const float* out_pw    = (const float*)d_in[10];
    float* out = (float*)d_out;

    const int smem_bytes = (C_DIM * TSTR + 4 * T_LEN * DIN + T_LEN * XP_OUT)
                           * (int)sizeof(float);   // 116480
    cudaFuncSetAttribute(mamba_fused_kernel,
                         cudaFuncAttributeMaxDynamicSharedMemorySize, smem_bytes);

    dim3 grid(2 * HW);
    dim3 block(NTHR);
    mamba_fused_kernel<<<grid, block, smem_bytes>>>(
        x, norm_w, in_proj_w, conv_w, conv_b, x_proj_w,
        dt_proj_w, dt_proj_b, A_log, Dp, out_pw, out);
}

// round 4
// speedup vs baseline: 1.5699x; 1.5699x over previous
#include <cuda_runtime.h>
#include <math.h>

#define T_LEN   16
#define C_DIM   192
#define DIN     384
#define DSTATE  16
#define DTRANK  12
#define XP_OUT  44
#define DB_STR  48       // padded db row stride
#define HW      784
#define NTHR    384
#define TSTR    20       // [c][t] stride (floats), 16B-aligned rows

__device__ __forceinline__ float siluf(float v) {
    return __fdividef(v, 1.0f + __expf(-v));
}

// smem layout (floats):
//   [0      , 3840 ) s_xn  [c][t]   (dead after B)
//   [3840   , 9984 ) s_u   [t][c]   u -> uc (in-place) 
//   [9984   , 17664) s_zy           z [t][c] (6144) ; later yT [c][t] (7680)
//   [17664  , 23808) s_dt  [t][c]   dt -> y (in-place)
//   [23808  , 24576) s_db  [t][48]
// total 24576 floats = 98304 B  -> 2 CTAs/SM
#define OFF_XN 0
#define OFF_U  3840
#define OFF_ZY 9984
#define OFF_DT 17664
#define OFF_DB 23808

__global__ __launch_bounds__(NTHR, 2)
void mamba_fused_kernel(const float* __restrict__ x,
                        const float* __restrict__ norm_w,
                        const float* __restrict__ in_proj_w,   // (192, 768)
                        const float* __restrict__ conv_w,      // (384, 4)
                        const float* __restrict__ conv_b,      // (384,)
                        const float* __restrict__ x_proj_w,    // (384, 44)
                        const float* __restrict__ dt_proj_w,   // (12, 384)
                        const float* __restrict__ dt_proj_b,   // (384,)
                        const float* __restrict__ A_log,       // (384, 16)
                        const float* __restrict__ Dp,          // (384,)
                        const float* __restrict__ out_proj_w,  // (384, 192)
                        float* __restrict__ out)
{
    extern __shared__ float sm[];
    float* s_xn = sm + OFF_XN;
    float* s_u  = sm + OFF_U;
    float* s_z  = sm + OFF_ZY;
    float* s_yT = sm + OFF_ZY;   // aliases z after scan
    float* s_dt = sm + OFF_DT;   // dt, then y[t][c]
    float* s_db = sm + OFF_DB;

    const int tid  = threadIdx.x;
    const int lane = tid & 31;
    const int wid  = tid >> 5;

    const int n  = blockIdx.x;
    const int b  = n / HW;
    const int hw = n - b * HW;
    const size_t tstride = (size_t)HW * C_DIM;
    const size_t base0   = ((size_t)b * T_LEN * HW + hw) * C_DIM;

    // ---------------- Phase A: load + RMSNorm -> s_xn[c][t] ----------------
    for (int t = wid; t < T_LEN; t += 12) {
        const float* row = x + base0 + (size_t)t * tstride;
        float v[6];
        float ss = 0.f;
        #pragma unroll
        for (int i = 0; i < 6; i++) { v[i] = row[lane + 32 * i]; ss = fmaf(v[i], v[i], ss); }
        #pragma unroll
        for (int o = 16; o; o >>= 1) ss += __shfl_xor_sync(0xffffffffu, ss, o);
        float nrm = rsqrtf(ss * (1.0f / 192.0f) + 1e-6f);
        #pragma unroll
        for (int i = 0; i < 6; i++) {
            int c = lane + 32 * i;
            s_xn[c * TSTR + t] = v[i] * nrm * norm_w[c];
        }
    }
    __syncthreads();

    // ---------------- Phase B: in_proj -> u (col tid), silu(z) (col tid+384)
    {
        float acc0[16], acc1[16];
        #pragma unroll
        for (int t = 0; t < 16; t++) { acc0[t] = 0.f; acc1[t] = 0.f; }
        #pragma unroll 2
        for (int k = 0; k < C_DIM; k++) {
            const float w0 = in_proj_w[k * 768 + tid];
            const float w1 = in_proj_w[k * 768 + tid + 384];
            const float4* xp = (const float4*)(s_xn + k * TSTR);
            #pragma unroll
            for (int q = 0; q < 4; q++) {
                float4 xv = xp[q];
                acc0[4*q+0] = fmaf(xv.x, w0, acc0[4*q+0]);
                acc0[4*q+1] = fmaf(xv.y, w0, acc0[4*q+1]);
                acc0[4*q+2] = fmaf(xv.z, w0, acc0[4*q+2]);
                acc0[4*q+3] = fmaf(xv.w, w0, acc0[4*q+3]);
                acc1[4*q+0] = fmaf(xv.x, w1, acc1[4*q+0]);
                acc1[4*q+1] = fmaf(xv.y, w1, acc1[4*q+1]);
                acc1[4*q+2] = fmaf(xv.z, w1, acc1[4*q+2]);
                acc1[4*q+3] = fmaf(xv.w, w1, acc1[4*q+3]);
            }
        }
        #pragma unroll
        for (int t = 0; t < 16; t++) {
            s_u[t * DIN + tid] = acc0[t];
            s_z[t * DIN + tid] = siluf(acc1[t]);
        }
    }
    // no sync: phase C touches only own column (written by this thread)

    // ---------------- Phase C: causal depthwise conv + silu, in-place on s_u
    {
        const int c = tid;
        const float4 cw = *(const float4*)(conv_w + c * 4);
        const float cb = conv_b[c];
        float um3 = 0.f, um2 = 0.f, um1 = 0.f;
        #pragma unroll
        for (int t = 0; t < T_LEN; t++) {
            float u0 = s_u[t * DIN + c];
            float acc = cb;
            acc = fmaf(um3, cw.x, acc);
            acc = fmaf(um2, cw.y, acc);
            acc = fmaf(um1, cw.z, acc);
            acc = fmaf(u0,  cw.w, acc);
            s_u[t * DIN + c] = siluf(acc);   // now uc
            um3 = um2; um2 = um1; um1 = u0;
        }
    }
    __syncthreads();   // D reads uc across columns

    // ---------------- Phase D: x_proj (16x384 @ 384x44) -> s_db ------------
    for (int t = wid; t < T_LEN; t += 12) {
        const float* ucr = s_u + t * DIN;
        const int j  = lane;
        const int j2 = lane + 32;
        const bool has2 = (j2 < XP_OUT);
        float a1 = 0.f, a2 = 0.f;
        #pragma unroll 4
        for (int k = 0; k < DIN; k += 4) {
            float4 uv = *(const float4*)(ucr + k);
            a1 = fmaf(uv.x, x_proj_w[(k + 0) * XP_OUT + j], a1);
            a1 = fmaf(uv.y, x_proj_w[(k + 1) * XP_OUT + j], a1);
            a1 = fmaf(uv.z, x_proj_w[(k + 2) * XP_OUT + j], a1);
            a1 = fmaf(uv.w, x_proj_w[(k + 3) * XP_OUT + j], a1);
            if (has2) {
                a2 = fmaf(uv.x, x_proj_w[(k + 0) * XP_OUT + j2], a2);
                a2 = fmaf(uv.y, x_proj_w[(k + 1) * XP_OUT + j2], a2);
                a2 = fmaf(uv.z, x_proj_w[(k + 2) * XP_OUT + j2], a2);
                a2 = fmaf(uv.w, x_proj_w[(k + 3) * XP_OUT + j2], a2);
            }
        }
        s_db[t * DB_STR + j] = a1;
        if (has2) s_db[t * DB_STR + j2] = a2;
    }
    __syncthreads();   // E/F read db across

    // ---------------- Phase E: dt_proj + softplus -> s_dt ------------------
    {
        const int c = tid;
        float wreg[DTRANK];
        #pragma unroll
        for (int r = 0; r < DTRANK; r++) wreg[r] = dt_proj_w[r * DIN + c];
        const float bias = dt_proj_b[c];
        #pragma unroll
        for (int t = 0; t < T_LEN; t++) {
            const float* dr = s_db + t * DB_STR;
            float acc = bias;
            #pragma unroll
            for (int r = 0; r < DTRANK; r++)
                acc = fmaf(dr[r], wreg[r], acc);
            float sp = (acc > 20.f) ? acc : log1pf(__expf(acc));
            s_dt[t * DIN + c] = sp;
        }
    }
    // no sync: scan reads dt/uc/z own column, db already synced

    // ---------------- Phase F: selective scan, y in-place over s_dt --------
    {
        const int c = tid;
        float A[DSTATE];
        {
            const float4* Ap = (const float4*)(A_log + c * DSTATE);
            #pragma unroll
            for (int q = 0; q < 4; q++) {
                float4 av = Ap[q];
                A[4*q+0] = -__expf(av.x); A[4*q+1] = -__expf(av.y);
                A[4*q+2] = -__expf(av.z); A[4*q+3] = -__expf(av.w);
            }
        }
        float h[DSTATE];
        #pragma unroll
        for (int s = 0; s < DSTATE; s++) h[s] = 0.f;
        const float Dc = Dp[c];

        #pragma unroll 1
        for (int t = 0; t < T_LEN; t++) {
            float dtv = s_dt[t * DIN + c];
            float ucv = s_u[t * DIN + c];
            float du  = dtv * ucv;
            const float4* B4 = (const float4*)(s_db + t * DB_STR + DTRANK);
            const float4* C4 = (const float4*)(s_db + t * DB_STR + DTRANK + DSTATE);
            float y = 0.f;
            #pragma unroll
            for (int q = 0; q < 4; q++) {
                float4 Bv = B4[q];
                float4 Cv = C4[q];
                float dA, hb;
                dA = __expf(dtv * A[4*q+0]); hb = fmaf(h[4*q+0], dA, du * Bv.x); h[4*q+0] = hb; y = fmaf(hb, Cv.x, y);
                dA = __expf(dtv * A[4*q+1]); hb = fmaf(h[4*q+1], dA, du * Bv.y); h[4*q+1] = hb; y = fmaf(hb, Cv.y, y);
                dA = __expf(dtv * A[4*q+2]); hb = fmaf(h[4*q+2], dA, du * Bv.z); h[4*q+2] = hb; y = fmaf(hb, Cv.z, y);
                dA = __expf(dtv * A[4*q+3]); hb = fmaf(h[4*q+3], dA, du * Bv.w); h[4*q+3] = hb; y = fmaf(hb, Cv.w, y);
            }
            y = fmaf(ucv, Dc, y);
            s_dt[t * DIN + c] = y * s_z[t * DIN + c];   // y[t][c] in place (own column)
        }
    }
    __syncthreads();   // everyone done reading z before yT overwrites it

    // ---------------- transpose y[t][c] -> s_yT[c][t] (aliases z) ----------
    {
        const int c = tid;
        float yv[16];
        #pragma unroll
        for (int t = 0; t < T_LEN; t++) yv[t] = s_dt[t * DIN + c];
        float4* dst = (float4*)(s_yT + c * TSTR);
        dst[0] = make_float4(yv[0],  yv[1],  yv[2],  yv[3]);
        dst[1] = make_float4(yv[4],  yv[5],  yv[6],  yv[7]);
        dst[2] = make_float4(yv[8],  yv[9],  yv[10], yv[11]);
        dst[3] = make_float4(yv[12], yv[13], yv[14], yv[15]);
    }
    __syncthreads();

    // ---------------- Phase G: out_proj + residual --------------------------
    {
        const int c  = (tid < C_DIM) ? tid : (tid - C_DIM);
        const int t0 = (tid < C_DIM) ? 0 : 8;
        float acc[8];
        #pragma unroll
        for (int i = 0; i < 8; i++) acc[i] = 0.f;
        #pragma unroll 2
        for (int k = 0; k < DIN; k++) {
            const float w = out_proj_w[k * C_DIM + c];
            const float4* yp = (const float4*)(s_yT + k * TSTR + t0);
            float4 y0 = yp[0];
            float4 y1 = yp[1];
            acc[0] = fmaf(y0.x, w, acc[0]);
            acc[1] = fmaf(y0.y, w, acc[1]);
            acc[2] = fmaf(y0.z, w, acc[2]);
            acc[3] = fmaf(y0.w, w, acc[3]);
            acc[4] = fmaf(y1.x, w, acc[4]);
            acc[5] = fmaf(y1.y, w, acc[5]);
            acc[6] = fmaf(y1.z, w, acc[6]);
            acc[7] = fmaf(y1.w, w, acc[7]);
        }
        #pragma unroll
        for (int i = 0; i < 8; i++) {
            size_t g = base0 + (size_t)(t0 + i) * tstride + c;
            out[g] = x[g] + acc[i];
        }
    }
}

extern "C" void kernel_launch(void* const* d_in, const int* in_sizes, int n_in,
                              void* d_out, int out_size)
{
    (void)in_sizes; (void)n_in; (void)out_size;
    const float* x         = (const float*)d_in[0];
    const float* norm_w    = (const float*)d_in[1];
    const float* in_proj_w = (const float*)d_in[2];
    const float* conv_w    = (const float*)d_in[3];
    const float* conv_b    = (const float*)d_in[4];
    const float* x_proj_w  = (const float*)d_in[5];
    const float* dt_proj_w = (const float*)d_in[6];
    const float* dt_proj_b = (const float*)d_in[7];
    const float* A_log     = (const float*)d_in[8];
    const float* Dp        = (const float*)d_in[9];
    const float* out_pw    = (const float*)d_in[10];
    float* out = (float*)d_out;

    const int smem_bytes = 24576 * (int)sizeof(float);   // 98304 B -> 2 CTAs/SM
    cudaFuncSetAttribute(mamba_fused_kernel,
                         cudaFuncAttributeMaxDynamicSharedMemorySize, smem_bytes);

    dim3 grid(2 * HW);
    dim3 block(NTHR);
    mamba_fused_kernel<<<grid, block, smem_bytes>>>(
        x, norm_w, in_proj_w, conv_w, conv_b, x_proj_w,
        dt_proj_w, dt_proj_b, A_log, Dp, out_pw, out);
}

// round 5
// speedup vs baseline: 1.9319x; 1.2306x over previous
#include <cuda_runtime.h>
#include <math.h>

#define T_LEN   16
#define C_DIM   192
#define DIN     384
#define DSTATE  16
#define DTRANK  12
#define XP_OUT  44
#define DB_STR  48
#define HW      784
#define NTHR    384
#define TSTR    20

__device__ __forceinline__ float siluf(float v) {
    return __fdividef(v, 1.0f + __expf(-v));
}

// smem layout (floats), total 24576 floats = 98304 B -> 2 CTAs/SM
#define OFF_XN 0        // [c][t] 192*20 = 3840   (dead after B)
#define OFF_U  3840     // [t][c] 16*384 = 6144   u -> uc in place
#define OFF_ZY 9984     // z [t][c] 6144 ; later yT [c][t] 7680
#define OFF_DT 17664    // dt -> y in place
#define OFF_DB 23808    // [t][48]

__global__ __launch_bounds__(NTHR, 2)
void mamba_fused_kernel(const float* __restrict__ x,
                        const float* __restrict__ norm_w,
                        const float* __restrict__ in_proj_w,   // (192, 768)
                        const float* __restrict__ conv_w,      // (384, 4)
                        const float* __restrict__ conv_b,      // (384,)
                        const float* __restrict__ x_proj_w,    // (384, 44)
                        const float* __restrict__ dt_proj_w,   // (12, 384)
                        const float* __restrict__ dt_proj_b,   // (384,)
                        const float* __restrict__ A_log,       // (384, 16)
                        const float* __restrict__ Dp,          // (384,)
                        const float* __restrict__ out_proj_w,  // (384, 192)
                        float* __restrict__ out)
{
    extern __shared__ float sm[];
    float* s_xn = sm + OFF_XN;
    float* s_u  = sm + OFF_U;
    float* s_z  = sm + OFF_ZY;
    float* s_yT = sm + OFF_ZY;
    float* s_dt = sm + OFF_DT;
    float* s_db = sm + OFF_DB;

    const int tid  = threadIdx.x;
    const int lane = tid & 31;
    const int wid  = tid >> 5;

    const int n  = blockIdx.x;
    const int b  = n / HW;
    const int hw = n - b * HW;
    const size_t tstride = (size_t)HW * C_DIM;
    const size_t base0   = ((size_t)b * T_LEN * HW + hw) * C_DIM;

    // ---------------- Phase A: load + RMSNorm -> s_xn[c][t] ----------------
    for (int t = wid; t < T_LEN; t += 12) {
        const float* row = x + base0 + (size_t)t * tstride;
        float v[6];
        float ss = 0.f;
        #pragma unroll
        for (int i = 0; i < 6; i++) { v[i] = row[lane + 32 * i]; ss = fmaf(v[i], v[i], ss); }
        #pragma unroll
        for (int o = 16; o; o >>= 1) ss += __shfl_xor_sync(0xffffffffu, ss, o);
        float nrm = rsqrtf(ss * (1.0f / 192.0f) + 1e-6f);
        #pragma unroll
        for (int i = 0; i < 6; i++) {
            int c = lane + 32 * i;
            s_xn[c * TSTR + t] = v[i] * nrm * norm_w[c];
        }
    }
    __syncthreads();

    // ---------------- Phase B: in_proj, software-pipelined weights ---------
    {
        const float* wp = in_proj_w + tid;
        float acc0[16], acc1[16];
        #pragma unroll
        for (int t = 0; t < 16; t++) { acc0[t] = 0.f; acc1[t] = 0.f; }

        float wa0 = wp[0],       wb0 = wp[384];
        float wa1 = wp[768],     wb1 = wp[768 + 384];

        #pragma unroll 2
        for (int k = 0; k < C_DIM; k += 2) {
            int kn = k + 2; if (kn >= C_DIM) kn = 0;   // safe dummy prefetch on last iter
            float nwa0 = wp[kn * 768],       nwb0 = wp[kn * 768 + 384];
            float nwa1 = wp[kn * 768 + 768], nwb1 = wp[kn * 768 + 768 + 384];

            const float4* xp0 = (const float4*)(s_xn + k * TSTR);
            const float4* xp1 = (const float4*)(s_xn + (k + 1) * TSTR);
            #pragma unroll
            for (int q = 0; q < 4; q++) {
                float4 x0 = xp0[q];
                float4 x1 = xp1[q];
                acc0[4*q+0] = fmaf(x0.x, wa0, acc0[4*q+0]);
                acc0[4*q+1] = fmaf(x0.y, wa0, acc0[4*q+1]);
                acc0[4*q+2] = fmaf(x0.z, wa0, acc0[4*q+2]);
                acc0[4*q+3] = fmaf(x0.w, wa0, acc0[4*q+3]);
                acc1[4*q+0] = fmaf(x0.x, wb0, acc1[4*q+0]);
                acc1[4*q+1] = fmaf(x0.y, wb0, acc1[4*q+1]);
                acc1[4*q+2] = fmaf(x0.z, wb0, acc1[4*q+2]);
                acc1[4*q+3] = fmaf(x0.w, wb0, acc1[4*q+3]);
                acc0[4*q+0] = fmaf(x1.x, wa1, acc0[4*q+0]);
                acc0[4*q+1] = fmaf(x1.y, wa1, acc0[4*q+1]);
                acc0[4*q+2] = fmaf(x1.z, wa1, acc0[4*q+2]);
                acc0[4*q+3] = fmaf(x1.w, wa1, acc0[4*q+3]);
                acc1[4*q+0] = fmaf(x1.x, wb1, acc1[4*q+0]);
                acc1[4*q+1] = fmaf(x1.y, wb1, acc1[4*q+1]);
                acc1[4*q+2] = fmaf(x1.z, wb1, acc1[4*q+2]);
                acc1[4*q+3] = fmaf(x1.w, wb1, acc1[4*q+3]);
            }
            wa0 = nwa0; wb0 = nwb0; wa1 = nwa1; wb1 = nwb1;
        }
        #pragma unroll
        for (int t = 0; t < 16; t++) {
            s_u[t * DIN + tid] = acc0[t];
            s_z[t * DIN + tid] = siluf(acc1[t]);
        }
    }
    // no sync needed: phase C touches only this thread's column

    // ---------------- Phase C: causal depthwise conv + silu, in place ------
    {
        const int c = tid;
        const float4 cw = *(const float4*)(conv_w + c * 4);
        const float cb = conv_b[c];
        float um3 = 0.f, um2 = 0.f, um1 = 0.f;
        #pragma unroll
        for (int t = 0; t < T_LEN; t++) {
            float u0 = s_u[t * DIN + c];
            float acc = cb;
            acc = fmaf(um3, cw.x, acc);
            acc = fmaf(um2, cw.y, acc);
            acc = fmaf(um1, cw.z, acc);
            acc = fmaf(u0,  cw.w, acc);
            s_u[t * DIN + c] = siluf(acc);
            um3 = um2; um2 = um1; um1 = u0;
        }
    }
    __syncthreads();

    // ---------------- Phase D: x_proj -> s_db ------------------------------
    // warp = timestep; lane l < 22 handles columns {2l, 2l+1} via float2 LDG
    if (lane < 22) {
        for (int t = wid; t < T_LEN; t += 12) {
            const float* ucr = s_u + t * DIN;
            const float2* wrow = (const float2*)x_proj_w + lane;  // row stride 22 float2
            float a0 = 0.f, a1 = 0.f;
            #pragma unroll 4
            for (int k = 0; k < DIN; k += 4) {
                float4 uv = *(const float4*)(ucr + k);
                float2 w0 = wrow[(k + 0) * 22];
                float2 w1 = wrow[(k + 1) * 22];
                float2 w2 = wrow[(k + 2) * 22];
                float2 w3 = wrow[(k + 3) * 22];
                a0 = fmaf(uv.x, w0.x, a0); a1 = fmaf(uv.x, w0.y, a1);
                a0 = fmaf(uv.y, w1.x, a0); a1 = fmaf(uv.y, w1.y, a1);
                a0 = fmaf(uv.z, w2.x, a0); a1 = fmaf(uv.z, w2.y, a1);
                a0 = fmaf(uv.w, w3.x, a0); a1 = fmaf(uv.w, w3.y, a1);
            }
            *(float2*)(s_db + t * DB_STR + 2 * lane) = make_float2(a0, a1);
        }
    }
    __syncthreads();

    // ---------------- Phase E: dt_proj + softplus -> s_dt ------------------
    {
        const int c = tid;
        float wreg[DTRANK];
        #pragma unroll
        for (int r = 0; r < DTRANK; r++) wreg[r] = dt_proj_w[r * DIN + c];
        const float bias = dt_proj_b[c];
        #pragma unroll
        for (int t = 0; t < T_LEN; t++) {
            const float4* dr = (const float4*)(s_db + t * DB_STR);
            float4 d0 = dr[0], d1 = dr[1], d2 = dr[2];
            float acc = bias;
            acc = fmaf(d0.x, wreg[0],  acc);
            acc = fmaf(d0.y, wreg[1],  acc);
            acc = fmaf(d0.z, wreg[2],  acc);
            acc = fmaf(d0.w, wreg[3],  acc);
            acc = fmaf(d1.x, wreg[4],  acc);
            acc = fmaf(d1.y, wreg[5],  acc);
            acc = fmaf(d1.z, wreg[6],  acc);
            acc = fmaf(d1.w, wreg[7],  acc);
            acc = fmaf(d2.x, wreg[8],  acc);
            acc = fmaf(d2.y, wreg[9],  acc);
            acc = fmaf(d2.z, wreg[10], acc);
            acc = fmaf(d2.w, wreg[11], acc);
            float sp = (acc > 20.f) ? acc : log1pf(__expf(acc));
            s_dt[t * DIN + c] = sp;
        }
    }
    // no sync: scan reads own column of dt/uc/z; db already synced

    // ---------------- Phase F: selective scan, y in-place over s_dt --------
    {
        const int c = tid;
        float A[DSTATE];
        {
            const float4* Ap = (const float4*)(A_log + c * DSTATE);
            #pragma unroll
            for (int q = 0; q < 4; q++) {
                float4 av = Ap[q];
                A[4*q+0] = -__expf(av.x); A[4*q+1] = -__expf(av.y);
                A[4*q+2] = -__expf(av.z); A[4*q+3] = -__expf(av.w);
            }
        }
        float h[DSTATE];
        #pragma unroll
        for (int s = 0; s < DSTATE; s++) h[s] = 0.f;
        const float Dc = Dp[c];

        #pragma unroll 1
        for (int t = 0; t < T_LEN; t++) {
            float dtv = s_dt[t * DIN + c];
            float ucv = s_u[t * DIN + c];
            float du  = dtv * ucv;
            const float4* B4 = (const float4*)(s_db + t * DB_STR + DTRANK);
            const float4* C4 = (const float4*)(s_db + t * DB_STR + DTRANK + DSTATE);
            float y = 0.f;
            #pragma unroll
            for (int q = 0; q < 4; q++) {
                float4 Bv = B4[q];
                float4 Cv = C4[q];
                float dA, hb;
                dA = __expf(dtv * A[4*q+0]); hb = fmaf(h[4*q+0], dA, du * Bv.x); h[4*q+0] = hb; y = fmaf(hb, Cv.x, y);
                dA = __expf(dtv * A[4*q+1]); hb = fmaf(h[4*q+1], dA, du * Bv.y); h[4*q+1] = hb; y = fmaf(hb, Cv.y, y);
                dA = __expf(dtv * A[4*q+2]); hb = fmaf(h[4*q+2], dA, du * Bv.z); h[4*q+2] = hb; y = fmaf(hb, Cv.z, y);
                dA = __expf(dtv * A[4*q+3]); hb = fmaf(h[4*q+3], dA, du * Bv.w); h[4*q+3] = hb; y = fmaf(hb, Cv.w, y);
            }
            y = fmaf(ucv, Dc, y);
            s_dt[t * DIN + c] = y * s_z[t * DIN + c];
        }
    }
    __syncthreads();

    // ---------------- transpose y[t][c] -> s_yT[c][t] (aliases z) ----------
    {
        const int c = tid;
        float yv[16];
        #pragma unroll
        for (int t = 0; t < T_LEN; t++) yv[t] = s_dt[t * DIN + c];
        float4* dst = (float4*)(s_yT + c * TSTR);
        dst[0] = make_float4(yv[0],  yv[1],  yv[2],  yv[3]);
        dst[1] = make_float4(yv[4],  yv[5],  yv[6],  yv[7]);
        dst[2] = make_float4(yv[8],  yv[9],  yv[10], yv[11]);
        dst[3] = make_float4(yv[12], yv[13], yv[14], yv[15]);
    }
    __syncthreads();

    // ---------------- Phase G: out_proj + residual, pipelined weights ------
    {
        const int c  = (tid < C_DIM) ? tid : (tid - C_DIM);
        const int t0 = (tid < C_DIM) ? 0 : 8;
        const float* wg = out_proj_w + c;
        float acc[8];
        #pragma unroll
        for (int i = 0; i < 8; i++) acc[i] = 0.f;

        float w0 = wg[0], w1 = wg[C_DIM];
        #pragma unroll 2
        for (int k = 0; k < DIN; k += 2) {
            int kn = k + 2; if (kn >= DIN) kn = 0;
            float nw0 = wg[kn * C_DIM];
            float nw1 = wg[kn * C_DIM + C_DIM];

            const float4* yp0 = (const float4*)(s_yT + k * TSTR + t0);
            const float4* yp1 = (const float4*)(s_yT + (k + 1) * TSTR + t0);
            float4 a0 = yp0[0], a1 = yp0[1];
            float4 b0 = yp1[0], b1 = yp1[1];
            acc[0] = fmaf(a0.x, w0, acc[0]);
            acc[1] = fmaf(a0.y, w0, acc[1]);
            acc[2] = fmaf(a0.z, w0, acc[2]);
            acc[3] = fmaf(a0.w, w0, acc[3]);
            acc[4] = fmaf(a1.x, w0, acc[4]);
            acc[5] = fmaf(a1.y, w0, acc[5]);
            acc[6] = fmaf(a1.z, w0, acc[6]);
            acc[7] = fmaf(a1.w, w0, acc[7]);
            acc[0] = fmaf(b0.x, w1, acc[0]);
            acc[1] = fmaf(b0.y, w1, acc[1]);
            acc[2] = fmaf(b0.z, w1, acc[2]);
            acc[3] = fmaf(b0.w, w1, acc[3]);
            acc[4] = fmaf(b1.x, w1, acc[4]);
            acc[5] = fmaf(b1.y, w1, acc[5]);
            acc[6] = fmaf(b1.z, w1, acc[6]);
            acc[7] = fmaf(b1.w, w1, acc[7]);
            w0 = nw0; w1 = nw1;
        }
        #pragma unroll
        for (int i = 0; i < 8; i++) {
            size_t g = base0 + (size_t)(t0 + i) * tstride + c;
            out[g] = x[g] + acc[i];
        }
    }
}

extern "C" void kernel_launch(void* const* d_in, const int* in_sizes, int n_in,
                              void* d_out, int out_size)
{
    (void)in_sizes; (void)n_in; (void)out_size;
    const float* x         = (const float*)d_in[0];
    const float* norm_w    = (const float*)d_in[1];
    const float* in_proj_w = (const float*)d_in[2];
    const float* conv_w    = (const float*)d_in[3];
    const float* conv_b    = (const float*)d_in[4];
    const float* x_proj_w  = (const float*)d_in[5];
    const float* dt_proj_w = (const float*)d_in[6];
    const float* dt_proj_b = (const float*)d_in[7];
    const float* A_log     = (const float*)d_in[8];
    const float* Dp        = (const float*)d_in[9];
    const float* out_pw    = (const float*)d_in[10];
    float* out = (float*)d_out;

    const int smem_bytes = 24576 * (int)sizeof(float);   // 98304 B -> 2 CTAs/SM
    cudaFuncSetAttribute(mamba_fused_kernel,
                         cudaFuncAttributeMaxDynamicSharedMemorySize, smem_bytes);

    dim3 grid(2 * HW);
    dim3 block(NTHR);
    mamba_fused_kernel<<<grid, block, smem_bytes>>>(
        x, norm_w, in_proj_w, conv_w, conv_b, x_proj_w,
        dt_proj_w, dt_proj_b, A_log, Dp, out_pw, out);
}